// round 10
// baseline (speedup 1.0000x reference)
#include <cuda_runtime.h>

// Problem constants
#define HWD 256
#define CH_STRIDE (HWD * HWD)   // 65536 floats per channel plane
#define HB 128                  // h-rows per CTA
#define THREADS 512

// Shared buffers:
//   bufA  [128][256]: Qs (phase 1) -> S/P (softmax, phase 3). Unpadded: accesses
//                     are row-internal vector or warp-uniform broadcast.
//   bufB  [64][260] : Kt chunks [64 dw][256 g] (phase 1) -> Vs chunks [64 g][256 w].
//   strip [128][64] : A-term strip for current w-chunk (fused from Kt-fill loads).
#define ST_A 256
#define ST_B 260
#define ST_S 64
#define BUFA_FLOATS (128 * ST_A)                 // 32768
#define BUFB_FLOATS (64 * ST_B)                  // 16640
#define STRIP_FLOATS (128 * ST_S)                // 8192
#define SMEM_FLOATS (BUFA_FLOATS + BUFB_FLOATS + STRIP_FLOATS)   // 57600
#define SMEM_BYTES  (SMEM_FLOATS * 4)                            // 230400

typedef unsigned long long u64;

__device__ __forceinline__ u64 pk2(float x, float y) {
    u64 r; asm("mov.b64 %0, {%1, %2};" : "=l"(r) : "f"(x), "f"(y)); return r;
}
__device__ __forceinline__ void upk2(u64 v, float &x, float &y) {
    asm("mov.b64 {%0, %1}, %2;" : "=f"(x), "=f"(y) : "l"(v));
}
// Packed dual-fp32 FMA: d = a * b + d. Only path to full fp32 rate on sm_103a.
__device__ __forceinline__ void fma2(u64 &d, u64 a, u64 b) {
    asm("fma.rn.f32x2 %0, %1, %2, %0;" : "+l"(d) : "l"(a), "l"(b));
}

__global__ void __launch_bounds__(THREADS, 1)
fused_conv_attn_kernel(const float* __restrict__ x1, const float* __restrict__ x2,
                       const float* __restrict__ Wq, const float* __restrict__ bq,
                       const float* __restrict__ Wk, const float* __restrict__ bk,
                       const float* __restrict__ Wv, const float* __restrict__ bv,
                       const float* __restrict__ Wa, const float* __restrict__ ba,
                       float* __restrict__ out)
{
    extern __shared__ float sm[];
    float* bufA  = sm;                               // Qs -> S/P
    float* bufB  = sm + BUFA_FLOATS;                 // Kt chunks -> Vs chunks
    float* strip = sm + BUFA_FLOATS + BUFB_FLOATS;   // A strip [128][64]

    const int o   = blockIdx.x;   // 0..31 output channel
    const int hb  = blockIdx.y;   // 0..1  h block
    const int b   = blockIdx.z;   // 0..31 batch
    const int tid = threadIdx.x;
    const int lane = tid & 31;
    const int warp = tid >> 5;    // warp owns rows 8*warp .. 8*warp+7
    const int c0   = 8 * lane;    // thread's 8 columns (distinct across lanes)

    const float* x1b = x1 + (size_t)b * 3 * CH_STRIDE;
    const float* x2b = x2 + (size_t)b * 3 * CH_STRIDE;
    const int h0g = hb * HB;

    // ---------------- Q fill: bufA[h][w] = Wq . x1[:,h,w] + bq (float4, coalesced)
    {
        const float w0 = Wq[o*3+0], w1 = Wq[o*3+1], w2 = Wq[o*3+2], bb = bq[o];
        const int wi = (tid & 63) * 4;
        const int hbase = (tid >> 6) * 16;
        #pragma unroll 4
        for (int k = 0; k < 16; ++k) {
            const int h = hbase + k;
            const float* p = x1b + (size_t)(h0g + h) * HWD + wi;
            float4 c0v = *(const float4*)(p);
            float4 c1v = *(const float4*)(p + CH_STRIDE);
            float4 c2v = *(const float4*)(p + 2 * CH_STRIDE);
            float4 r;
            r.x = bb + w0*c0v.x + w1*c1v.x + w2*c2v.x;
            r.y = bb + w0*c0v.y + w1*c1v.y + w2*c2v.y;
            r.z = bb + w0*c0v.z + w1*c1v.z + w2*c2v.z;
            r.w = bb + w0*c0v.w + w1*c1v.w + w2*c2v.w;
            *(float4*)&bufA[h * ST_A + wi] = r;
        }
    }

    // ---------------- Phase 1: S[128h][256g] in registers, 8h x 8g per thread.
    // Warp reads 8 q values (uniform broadcast) + 1KB of distinct K per dw step:
    // 0.5 B/lane-FMA crossbar traffic (no duplicated reads across lanes).
    u64 sacc[8][4];
    #pragma unroll
    for (int i = 0; i < 8; ++i)
        #pragma unroll
        for (int m = 0; m < 4; ++m) sacc[i][m] = 0ull;

    const u64 k256 = pk2(256.0f, 256.0f);

    for (int wt = 0; wt < 4; ++wt) {
        if (wt > 0) __syncthreads();   // previous GEMM+fold done reading bufB/strip

        // Kt fill + A strip: lanes along w (coalesced float2 LDG),
        // transposed STS.32 into bufB[dw][g].
        {
            const float k0w = Wk[o*3+0], k1w = Wk[o*3+1], k2w = Wk[o*3+2], bbk = bk[o];
            const float a0w = Wa[o*3+0], a1w = Wa[o*3+1], a2w = Wa[o*3+2], bba = ba[o];
            const int dw = 2 * lane;
            #pragma unroll 4
            for (int k = 0; k < 16; ++k) {
                const int g = warp * 16 + k;
                const float* p = x2b + (size_t)g * HWD + wt * 64 + dw;
                float2 c0v = *(const float2*)(p);
                float2 c1v = *(const float2*)(p + CH_STRIDE);
                float2 c2v = *(const float2*)(p + 2 * CH_STRIDE);
                bufB[dw * ST_B + g]       = bbk + k0w*c0v.x + k1w*c1v.x + k2w*c2v.x;
                bufB[(dw + 1) * ST_B + g] = bbk + k0w*c0v.y + k1w*c1v.y + k2w*c2v.y;
                const int hloc = g - h0g;
                if ((unsigned)hloc < 128u) {   // warp-uniform branch
                    float2 a;
                    a.x = bba + a0w*c0v.x + a1w*c1v.x + a2w*c2v.x;
                    a.y = bba + a0w*c0v.y + a1w*c1v.y + a2w*c2v.y;
                    *(float2*)&strip[hloc * ST_S + dw] = a;
                }
            }
        }
        __syncthreads();

        // GEMM over this w chunk
        const int wbase = wt * 64;
        const float* qcol0 = &bufA[(warp * 8) * ST_A + wbase];
        #pragma unroll 2
        for (int dw = 0; dw < 64; ++dw) {
            const float* kr = &bufB[dw * ST_B + c0];
            ulonglong2 Ka = *(const ulonglong2*)(kr);
            ulonglong2 Kb = *(const ulonglong2*)(kr + 4);
            const float* qc = qcol0 + dw;
            #pragma unroll
            for (int i = 0; i < 8; ++i) {
                float q = qc[i * ST_A];        // warp-uniform broadcast
                u64 qq = pk2(q, q);
                fma2(sacc[i][0], qq, Ka.x); fma2(sacc[i][1], qq, Ka.y);
                fma2(sacc[i][2], qq, Kb.x); fma2(sacc[i][3], qq, Kb.y);
            }
        }

        // Fold A strip: thread's cols c0..c0+7 lie in chunk wt iff lane>>3 == wt.
        // sacc += 256*A (x256 here, x(1/256) in epilogue: both exact).
        if ((lane >> 3) == wt) {
            const int dwc = 8 * (lane & 7);
            #pragma unroll
            for (int i = 0; i < 8; ++i) {
                const float* sp = &strip[(warp * 8 + i) * ST_S + dwc];
                float4 a0 = *(const float4*)(sp);
                float4 a1 = *(const float4*)(sp + 4);
                fma2(sacc[i][0], pk2(a0.x, a0.y), k256);
                fma2(sacc[i][1], pk2(a0.z, a0.w), k256);
                fma2(sacc[i][2], pk2(a1.x, a1.y), k256);
                fma2(sacc[i][3], pk2(a1.z, a1.w), k256);
            }
        }
    }

    // ---------------- Epilogue: S = sacc/256 -> bufA rows 8*warp..+7 (warp-private)
    {
        const float inv = 1.0f / 256.0f;
        #pragma unroll
        for (int i = 0; i < 8; ++i) {
            float s0, s1, s2, s3, s4, s5, s6, s7;
            upk2(sacc[i][0], s0, s1); upk2(sacc[i][1], s2, s3);
            upk2(sacc[i][2], s4, s5); upk2(sacc[i][3], s6, s7);
            float* dst = &bufA[(warp * 8 + i) * ST_A + c0];
            float4 r0, r1;
            r0.x = s0*inv; r0.y = s1*inv; r0.z = s2*inv; r0.w = s3*inv;
            r1.x = s4*inv; r1.y = s5*inv; r1.z = s6*inv; r1.w = s7*inv;
            *(float4*)(dst)     = r0;
            *(float4*)(dst + 4) = r1;
        }
    }
    __syncwarp();

    // ---------------- Softmax in place (warp per 8 rows; rows warp-private)
    {
        #pragma unroll 2
        for (int rr = 0; rr < 8; ++rr) {
            float* row = &bufA[(warp * 8 + rr) * ST_A];
            float4 v0 = *(float4*)&row[lane * 4];
            float4 v1 = *(float4*)&row[128 + lane * 4];
            float m = fmaxf(fmaxf(fmaxf(v0.x, v0.y), fmaxf(v0.z, v0.w)),
                            fmaxf(fmaxf(v1.x, v1.y), fmaxf(v1.z, v1.w)));
            #pragma unroll
            for (int off = 16; off; off >>= 1)
                m = fmaxf(m, __shfl_xor_sync(0xffffffffu, m, off));
            v0.x = __expf(v0.x - m); v0.y = __expf(v0.y - m);
            v0.z = __expf(v0.z - m); v0.w = __expf(v0.w - m);
            v1.x = __expf(v1.x - m); v1.y = __expf(v1.y - m);
            v1.z = __expf(v1.z - m); v1.w = __expf(v1.w - m);
            float s = v0.x + v0.y + v0.z + v0.w + v1.x + v1.y + v1.z + v1.w;
            #pragma unroll
            for (int off = 16; off; off >>= 1)
                s += __shfl_xor_sync(0xffffffffu, s, off);
            const float rinv = 1.0f / s;
            v0.x *= rinv; v0.y *= rinv; v0.z *= rinv; v0.w *= rinv;
            v1.x *= rinv; v1.y *= rinv; v1.z *= rinv; v1.w *= rinv;
            *(float4*)&row[lane * 4] = v0;
            *(float4*)&row[128 + lane * 4] = v1;
        }
    }
    __syncwarp();   // P rows warp-private; cross-lane broadcast reads in phase 3

    // ---------------- Phase 3: O = P V, g tiled in 64-chunks; Vs in bufB.
    u64 oacc[8][4];
    #pragma unroll
    for (int i = 0; i < 8; ++i)
        #pragma unroll
        for (int m = 0; m < 4; ++m) oacc[i][m] = 0ull;

    for (int gt = 0; gt < 4; ++gt) {
        __syncthreads();   // phase-1 Kt reads done (gt=0) / previous Vs reads done

        // V fill: bufB[g][w] = Wv . x2[:, gt*64+g, w] + bv (float4, coalesced)
        {
            const float w0 = Wv[o*3+0], w1 = Wv[o*3+1], w2 = Wv[o*3+2], bb = bv[o];
            const int wi = (tid & 63) * 4;
            const int gbase = (tid >> 6) * 8;
            #pragma unroll 4
            for (int k = 0; k < 8; ++k) {
                const int g = gbase + k;
                const float* p = x2b + (size_t)(gt * 64 + g) * HWD + wi;
                float4 c0v = *(const float4*)(p);
                float4 c1v = *(const float4*)(p + CH_STRIDE);
                float4 c2v = *(const float4*)(p + 2 * CH_STRIDE);
                float4 r;
                r.x = bb + w0*c0v.x + w1*c1v.x + w2*c2v.x;
                r.y = bb + w0*c0v.y + w1*c1v.y + w2*c2v.y;
                r.z = bb + w0*c0v.z + w1*c1v.z + w2*c2v.z;
                r.w = bb + w0*c0v.w + w1*c1v.w + w2*c2v.w;
                *(float4*)&bufB[g * ST_B + wi] = r;
            }
        }
        __syncthreads();

        const float* prow0 = &bufA[(warp * 8) * ST_A + gt * 64];
        #pragma unroll 2
        for (int g = 0; g < 64; ++g) {
            const float* vr = &bufB[g * ST_B + c0];
            ulonglong2 Va = *(const ulonglong2*)(vr);
            ulonglong2 Vb = *(const ulonglong2*)(vr + 4);
            const float* pc = prow0 + g;
            #pragma unroll
            for (int i = 0; i < 8; ++i) {
                float p = pc[i * ST_A];        // warp-uniform broadcast
                u64 pp = pk2(p, p);
                fma2(oacc[i][0], pp, Va.x); fma2(oacc[i][1], pp, Va.y);
                fma2(oacc[i][2], pp, Vb.x); fma2(oacc[i][3], pp, Vb.y);
            }
        }
    }

    // ---------------- Output: [b][o][h][w]; warp covers 1KB per row, coalesced
    float* ob = out + ((size_t)(b * 32 + o) * HWD + h0g) * HWD;
    #pragma unroll
    for (int i = 0; i < 8; ++i) {
        const int h = warp * 8 + i;
        float r0x, r0y, r0z, r0w, r1x, r1y, r1z, r1w;
        upk2(oacc[i][0], r0x, r0y); upk2(oacc[i][1], r0z, r0w);
        upk2(oacc[i][2], r1x, r1y); upk2(oacc[i][3], r1z, r1w);
        float* dst = &ob[(size_t)h * HWD + c0];
        *(float4*)(dst)     = make_float4(r0x, r0y, r0z, r0w);
        *(float4*)(dst + 4) = make_float4(r1x, r1y, r1z, r1w);
    }
}

extern "C" void kernel_launch(void* const* d_in, const int* in_sizes, int n_in,
                              void* d_out, int out_size)
{
    const float* x1 = (const float*)d_in[0];
    const float* x2 = (const float*)d_in[1];
    const float* Wq = (const float*)d_in[2];
    const float* bq = (const float*)d_in[3];
    const float* Wk = (const float*)d_in[4];
    const float* bk = (const float*)d_in[5];
    const float* Wv = (const float*)d_in[6];
    const float* bv = (const float*)d_in[7];
    const float* Wa = (const float*)d_in[8];
    const float* ba = (const float*)d_in[9];
    float* out = (float*)d_out;

    cudaFuncSetAttribute(fused_conv_attn_kernel,
                         cudaFuncAttributeMaxDynamicSharedMemorySize, SMEM_BYTES);

    dim3 grid(32, 2, 32);   // (o, h-block, b): consecutive CTAs share b -> x2[b] L2-resident
    fused_conv_attn_kernel<<<grid, THREADS, SMEM_BYTES>>>(
        x1, x2, Wq, bq, Wk, bk, Wv, bv, Wa, ba, out);
}